// round 11
// baseline (speedup 1.0000x reference)
#include <cuda_runtime.h>
#include <cuda_bf16.h>
#include <cuda_fp16.h>
#include <cstdint>

// TimeAwareFullAttention: B=8, H=8, L=S=1024, E=64, fp32.
// Two kernels:
//  1) prepass: K fp32 -> single fp16, V fp32 -> fp16 transposed,
//     written to __device__ scratch in the exact per-tile smem layout.
//  2) main: flash attention, 256 threads / 64 q-rows, 8 warps (4M x 2N),
//     two CTAs per SM. QK^T: Q split-fp16 2-term (exact pair) x K fp16
//     (error only from K rounding ~2^-12 -> ~3e-4). PV fp16.
//     log2e+decay folded into Q, exp bias folded into S accumulator init
//     -> p = ex2(sacc). cp.async 3-stage pipeline, ldmatrix.x4 loads.
// No max-subtraction (logits bounded); O accumulates in fp32 registers.

#define FACTOR_INV 0.2f
#define QSCALE_L2  0.6451986757929906f   // (1/sqrt(5)) * log2(e)
#define EXP2_BIAS  (-18.0f)

constexpr int NTILES = 16;                 // 1024 / 64
constexpr int KST    = 72;                 // row stride, elems (144 B)
constexpr int ROWB   = 144;                // row stride, bytes
constexpr uint32_t ARR_B   = 64u * KST * 2u;    // 9216 B per array
constexpr uint32_t TILE_B  = 2u * ARR_B;        // Kh, Vh = 18432 B
constexpr uint32_t SMEM_B  = 3u * TILE_B;       // 3-stage = 55296 B
constexpr uint32_t CHUNKS  = TILE_B / 16u;      // 1152 x 16B per tile

// scratch: [64 bh][16 tiles][18432 B] = 18.9 MB (L2-resident)
__device__ __align__(128) unsigned char g_scratch[64ull * 16ull * TILE_B];

// ---------------- helpers ----------------
__device__ __forceinline__ void mma_f16(float c[4],
        uint32_t a0, uint32_t a1, uint32_t a2, uint32_t a3,
        uint32_t b0, uint32_t b1)
{
    asm volatile(
        "mma.sync.aligned.m16n8k16.row.col.f32.f16.f16.f32 "
        "{%0,%1,%2,%3}, {%4,%5,%6,%7}, {%8,%9}, {%0,%1,%2,%3};"
        : "+f"(c[0]), "+f"(c[1]), "+f"(c[2]), "+f"(c[3])
        : "r"(a0), "r"(a1), "r"(a2), "r"(a3), "r"(b0), "r"(b1));
}
__device__ __forceinline__ void ldsm4(uint32_t r[4], uint32_t addr)
{
    asm volatile(
        "ldmatrix.sync.aligned.m8n8.x4.shared.b16 {%0,%1,%2,%3}, [%4];"
        : "=r"(r[0]), "=r"(r[1]), "=r"(r[2]), "=r"(r[3]) : "r"(addr));
}
__device__ __forceinline__ void cpasync16(uint32_t dst, const void* src)
{
    asm volatile("cp.async.cg.shared.global [%0], [%1], 16;"
                 :: "r"(dst), "l"(src));
}
__device__ __forceinline__ void cp_commit()
{
    asm volatile("cp.async.commit_group;");
}
__device__ __forceinline__ void cp_wait1()
{
    asm volatile("cp.async.wait_group 1;");
}
__device__ __forceinline__ uint32_t s2u(const void* p)
{
    uint32_t a;
    asm("{ .reg .u64 t; cvta.to.shared.u64 t, %1; cvt.u32.u64 %0, t; }"
        : "=r"(a) : "l"(p));
    return a;
}
__device__ __forceinline__ float ex2f(float x)
{
    float r;
    asm("ex2.approx.f32 %0, %1;" : "=f"(r) : "f"(x));
    return r;
}
__device__ __forceinline__ uint32_t packh2(float x0, float x1)
{
    __half2 h = __floats2half2_rn(x0, x1);
    return *(uint32_t*)&h;
}
// exact fp16 split of (x0,x1): h = fp16(x), l = fp16(x - h); h+l == x to 2^-24
__device__ __forceinline__ void splitpk_h(float x0, float x1,
                                          uint32_t& h, uint32_t& l)
{
    __half h0 = __float2half_rn(x0);
    __half h1 = __float2half_rn(x1);
    __half l0 = __float2half_rn(x0 - __half2float(h0));
    __half l1 = __float2half_rn(x1 - __half2float(h1));
    __half2 hh; hh.x = h0; hh.y = h1;
    __half2 ll; ll.x = l0; ll.y = l1;
    h = *(uint32_t*)&hh;
    l = *(uint32_t*)&ll;
}

// ---------------- prepass: convert K/V once into scratch ----------------
__global__ void __launch_bounds__(256, 4)
ta_prepass(const float* __restrict__ K, const float* __restrict__ V)
{
    extern __shared__ char ps[];
    const int tid  = threadIdx.x;
    const int tile = blockIdx.x;
    const int bh   = blockIdx.y;

    const float* Kt = K + ((size_t)bh * 1024 + (size_t)tile * 64) * 64;
    const float* Vt = V + ((size_t)bh * 1024 + (size_t)tile * 64) * 64;

    __half* Kh = (__half*)ps;                 // [kv][e], 64 x KST
    __half* Vh = (__half*)(ps + ARR_B);       // V^T: [e][kv], 64 x KST

    #pragma unroll
    for (int it = 0; it < 4; it++) {
        int i = tid + it * 256;
        int r = i >> 4, e4 = (i & 15) << 2;
        float4 kv = *(const float4*)(Kt + (size_t)r * 64 + e4);
        *(uint32_t*)&Kh[r * KST + e4]     = packh2(kv.x, kv.y);
        *(uint32_t*)&Kh[r * KST + e4 + 2] = packh2(kv.z, kv.w);
        float4 vv = *(const float4*)(Vt + (size_t)r * 64 + e4);
        Vh[(e4 + 0) * KST + r] = __float2half_rn(vv.x);
        Vh[(e4 + 1) * KST + r] = __float2half_rn(vv.y);
        Vh[(e4 + 2) * KST + r] = __float2half_rn(vv.z);
        Vh[(e4 + 3) * KST + r] = __float2half_rn(vv.w);
    }
    __syncthreads();

    unsigned char* dst = g_scratch + ((size_t)bh * 16 + tile) * TILE_B;
    for (uint32_t i = tid; i < CHUNKS; i += 256)
        *(float4*)(dst + i * 16) = *(const float4*)(ps + i * 16);
}

// ---------------- main kernel: 64 q-rows per CTA, 2 CTAs/SM ----------------
__global__ void __launch_bounds__(256, 2)
ta_attn_mma6(const float* __restrict__ Q, const float* __restrict__ TD,
             float* __restrict__ O)
{
    extern __shared__ char sm[];
    const uint32_t sbase = s2u(sm);

    const int tid  = threadIdx.x;
    const int warp = tid >> 5;
    const int lane = tid & 31;
    const int g    = lane >> 2;
    const int qd   = lane & 3;
    const int wm   = warp & 3;       // M slice: q rows wm*16 .. +15
    const int wn   = warp >> 2;      // N half:  kv cols wn*32 .. +31

    const int qt = blockIdx.x;       // q tile (0..15), 64 rows each
    const int bh = blockIdx.y;       // b*8+h (0..63)
    const int b  = bh >> 3;

    const float* Qb  = Q  + ((size_t)bh * 1024 + (size_t)qt * 64) * 64;
    const float* tdb = TD + (size_t)b * 1024 + (size_t)qt * 64;
    float*       Ob  = O  + ((size_t)bh * 1024 + (size_t)qt * 64) * 64;
    const unsigned char* src0 = g_scratch + (size_t)bh * 16 * TILE_B;

    const int ra = wm * 16 + g;      // accum rows ra, ra+8
    const int rb = ra + 8;

    // ldmatrix per-lane offset: rows (L&7)+((L>>4)<<3), +16B for bit3
    const uint32_t lmoff = (uint32_t)(((lane & 7) + ((lane >> 4) << 3)) * ROWB
                                      + ((lane >> 3) & 1) * 16);

    // ---- cp.async prologue: tiles 0 and 1 into stages 0,1 ----
    #pragma unroll
    for (int pt = 0; pt < 2; pt++) {
        uint32_t dst = sbase + pt * TILE_B;
        const unsigned char* src = src0 + (size_t)pt * TILE_B;
        for (uint32_t i = tid; i < CHUNKS; i += 256)
            cpasync16(dst + i * 16, src + i * 16);
        cp_commit();
    }

    // ---- Q A-fragments: exact fp16 pair, decay*SCALE*log2e folded ----
    uint32_t qh[4][4], ql[4][4];
    {
        const float ca = QSCALE_L2 * __expf(-tdb[ra] * FACTOR_INV);
        const float cb = QSCALE_L2 * __expf(-tdb[rb] * FACTOR_INV);
        #pragma unroll
        for (int k = 0; k < 4; k++) {
            int e = 16 * k + 2 * qd;
            float2 xa0 = *(const float2*)(Qb + (size_t)ra * 64 + e);
            float2 xb0 = *(const float2*)(Qb + (size_t)rb * 64 + e);
            float2 xa1 = *(const float2*)(Qb + (size_t)ra * 64 + e + 8);
            float2 xb1 = *(const float2*)(Qb + (size_t)rb * 64 + e + 8);
            splitpk_h(xa0.x * ca, xa0.y * ca, qh[k][0], ql[k][0]);
            splitpk_h(xb0.x * cb, xb0.y * cb, qh[k][1], ql[k][1]);
            splitpk_h(xa1.x * ca, xa1.y * ca, qh[k][2], ql[k][2]);
            splitpk_h(xb1.x * cb, xb1.y * cb, qh[k][3], ql[k][3]);
        }
    }

    float oacc[8][4];
    #pragma unroll
    for (int j = 0; j < 8; j++)
        #pragma unroll
        for (int c = 0; c < 4; c++) oacc[j][c] = 0.0f;
    float lsA = 0.0f, lsB = 0.0f;

    for (int t = 0; t < NTILES; t++) {
        cp_wait1();            // tile t landed (t+1 may be in flight)
        __syncthreads();

        // ---- issue tile t+2 into stage (t+2)%3 (its readers retired) ----
        if (t + 2 < NTILES) {
            uint32_t dst = sbase + ((t + 2) % 3) * TILE_B;
            const unsigned char* src = src0 + (size_t)(t + 2) * TILE_B;
            for (uint32_t i = tid; i < CHUNKS; i += 256)
                cpasync16(dst + i * 16, src + i * 16);
        }
        cp_commit();           // always commit to keep group accounting fixed

        const uint32_t buf = sbase + (t % 3) * TILE_B;
        const uint32_t kqb = buf + wn * (32 * ROWB) + lmoff;      // Kh half
        const uint32_t vvb = buf + ARR_B + wn * 64 + lmoff;       // Vh half

        // ---- S' = log2e*z - 18:  (qh + ql) x Kh, 2 fp16 terms ----
        float sacc[4][4];
        #pragma unroll
        for (int j = 0; j < 4; j++)
            #pragma unroll
            for (int c = 0; c < 4; c++) sacc[j][c] = EXP2_BIAS;

        #pragma unroll
        for (int k = 0; k < 4; k++) {
            #pragma unroll
            for (int jp = 0; jp < 2; jp++) {
                uint32_t b4[4];
                ldsm4(b4, kqb + jp * (16 * ROWB) + k * 32);
                mma_f16(sacc[2*jp],   qh[k][0], qh[k][1], qh[k][2], qh[k][3],
                        b4[0], b4[1]);
                mma_f16(sacc[2*jp],   ql[k][0], ql[k][1], ql[k][2], ql[k][3],
                        b4[0], b4[1]);
                mma_f16(sacc[2*jp+1], qh[k][0], qh[k][1], qh[k][2], qh[k][3],
                        b4[2], b4[3]);
                mma_f16(sacc[2*jp+1], ql[k][0], ql[k][1], ql[k][2], ql[k][3],
                        b4[2], b4[3]);
            }
        }

        // ---- p = 2^(sacc) directly; pack fp16 ----
        uint32_t ph[2][4];
        #pragma unroll
        for (int j = 0; j < 4; j++) {
            sacc[j][0] = ex2f(sacc[j][0]);
            sacc[j][1] = ex2f(sacc[j][1]);
            sacc[j][2] = ex2f(sacc[j][2]);
            sacc[j][3] = ex2f(sacc[j][3]);
            lsA += sacc[j][0] + sacc[j][1];
            lsB += sacc[j][2] + sacc[j][3];
        }
        #pragma unroll
        for (int kk = 0; kk < 2; kk++) {
            ph[kk][0] = packh2(sacc[2*kk][0],   sacc[2*kk][1]);
            ph[kk][1] = packh2(sacc[2*kk][2],   sacc[2*kk][3]);
            ph[kk][2] = packh2(sacc[2*kk+1][0], sacc[2*kk+1][1]);
            ph[kk][3] = packh2(sacc[2*kk+1][2], sacc[2*kk+1][3]);
        }

        // ---- O += P V over this warp's kv half (fp16), ldmatrix V frags ----
        #pragma unroll
        for (int kk = 0; kk < 2; kk++) {
            #pragma unroll
            for (int jp = 0; jp < 4; jp++) {
                uint32_t v4[4];
                ldsm4(v4, vvb + jp * (16 * ROWB) + kk * 32);
                mma_f16(oacc[2*jp],   ph[kk][0], ph[kk][1], ph[kk][2], ph[kk][3],
                        v4[0], v4[1]);
                mma_f16(oacc[2*jp+1], ph[kk][0], ph[kk][1], ph[kk][2], ph[kk][3],
                        v4[2], v4[3]);
            }
        }
    }

    // ---- quad-reduce row sums ----
    lsA += __shfl_xor_sync(0xffffffffu, lsA, 1);
    lsA += __shfl_xor_sync(0xffffffffu, lsA, 2);
    lsB += __shfl_xor_sync(0xffffffffu, lsB, 1);
    lsB += __shfl_xor_sync(0xffffffffu, lsB, 2);

    __syncthreads();   // all warps done with smem buffers before reuse

    // ---- epilogue: reduce O and lsum across the two N-halves via smem ----
    float* stage  = (float*)sm;              // 16 KB
    float* lstage = (float*)(sm + 16384);    // 256 B
    if (wn == 1) {
        #pragma unroll
        for (int j = 0; j < 8; j++) {
            float4 v4 = make_float4(oacc[j][0], oacc[j][1],
                                    oacc[j][2], oacc[j][3]);
            *(float4*)&stage[((wm * 8 + j) * 32 + lane) * 4] = v4;
        }
        lstage[ra] = lsA;
        lstage[rb] = lsB;
    }
    __syncthreads();
    if (wn == 0) {
        float invA = 1.0f / (lsA + lstage[ra]);
        float invB = 1.0f / (lsB + lstage[rb]);
        #pragma unroll
        for (int j = 0; j < 8; j++) {
            float4 p4 = *(float4*)&stage[((wm * 8 + j) * 32 + lane) * 4];
            float2 oa, ob;
            oa.x = (oacc[j][0] + p4.x) * invA;
            oa.y = (oacc[j][1] + p4.y) * invA;
            ob.x = (oacc[j][2] + p4.z) * invB;
            ob.y = (oacc[j][3] + p4.w) * invB;
            *(float2*)(Ob + (size_t)ra * 64 + 8 * j + 2 * qd) = oa;
            *(float2*)(Ob + (size_t)rb * 64 + 8 * j + 2 * qd) = ob;
        }
    }
}

extern "C" void kernel_launch(void* const* d_in, const int* in_sizes, int n_in,
                              void* d_out, int out_size)
{
    const float* Q  = (const float*)d_in[0];
    const float* K  = (const float*)d_in[1];
    const float* V  = (const float*)d_in[2];
    const float* TD = (const float*)d_in[3];
    float* O = (float*)d_out;

    cudaFuncSetAttribute(ta_prepass,
                         cudaFuncAttributeMaxDynamicSharedMemorySize, TILE_B);
    cudaFuncSetAttribute(ta_attn_mma6,
                         cudaFuncAttributeMaxDynamicSharedMemorySize, SMEM_B);

    dim3 pgrid(16, 64);   // 16 kv tiles x 64 (b,h)
    ta_prepass<<<pgrid, 256, TILE_B>>>(K, V);

    dim3 grid(16, 64);    // 16 q-tiles (64 rows) x 64 (b,h); 2 CTAs/SM
    ta_attn_mma6<<<grid, 256, SMEM_B>>>(Q, TD, O);
}

// round 12
// speedup vs baseline: 1.0073x; 1.0073x over previous
#include <cuda_runtime.h>
#include <cuda_bf16.h>
#include <cuda_fp16.h>
#include <cstdint>

// TimeAwareFullAttention: B=8, H=8, L=S=1024, E=64, fp32.
// Two kernels:
//  1) prepass: K fp32 -> single fp16, V fp32 -> fp16 transposed,
//     written to __device__ scratch in the exact per-tile smem layout.
//  2) main: flash attention, 256 threads / 64 q-rows, 8 warps (4M x 2N),
//     two CTAs per SM. QK^T: Q split-fp16 2-term (exact pair) x K fp16
//     (error only from K rounding ~2^-12 -> ~3e-4). PV fp16.
//     log2e+decay folded into Q, exp bias folded into S accumulator init
//     -> p = ex2(sacc). cp.async 3-stage pipeline, ldmatrix.x4 loads.
// No max-subtraction (logits bounded); O accumulates in fp32 registers.

#define FACTOR_INV 0.2f
#define QSCALE_L2  0.6451986757929906f   // (1/sqrt(5)) * log2(e)
#define EXP2_BIAS  (-18.0f)

constexpr int NTILES = 16;                 // 1024 / 64
constexpr int KST    = 72;                 // row stride, elems (144 B)
constexpr int ROWB   = 144;                // row stride, bytes
constexpr uint32_t ARR_B   = 64u * KST * 2u;    // 9216 B per array
constexpr uint32_t TILE_B  = 2u * ARR_B;        // Kh, Vh = 18432 B
constexpr uint32_t SMEM_B  = 3u * TILE_B;       // 3-stage = 55296 B
constexpr uint32_t CHUNKS  = TILE_B / 16u;      // 1152 x 16B per tile

// scratch: [64 bh][16 tiles][18432 B] = 18.9 MB (L2-resident)
__device__ __align__(128) unsigned char g_scratch[64ull * 16ull * TILE_B];

// ---------------- helpers ----------------
__device__ __forceinline__ void mma_f16(float c[4],
        uint32_t a0, uint32_t a1, uint32_t a2, uint32_t a3,
        uint32_t b0, uint32_t b1)
{
    asm volatile(
        "mma.sync.aligned.m16n8k16.row.col.f32.f16.f16.f32 "
        "{%0,%1,%2,%3}, {%4,%5,%6,%7}, {%8,%9}, {%0,%1,%2,%3};"
        : "+f"(c[0]), "+f"(c[1]), "+f"(c[2]), "+f"(c[3])
        : "r"(a0), "r"(a1), "r"(a2), "r"(a3), "r"(b0), "r"(b1));
}
__device__ __forceinline__ void ldsm4(uint32_t r[4], uint32_t addr)
{
    asm volatile(
        "ldmatrix.sync.aligned.m8n8.x4.shared.b16 {%0,%1,%2,%3}, [%4];"
        : "=r"(r[0]), "=r"(r[1]), "=r"(r[2]), "=r"(r[3]) : "r"(addr));
}
__device__ __forceinline__ void cpasync16(uint32_t dst, const void* src)
{
    asm volatile("cp.async.cg.shared.global [%0], [%1], 16;"
                 :: "r"(dst), "l"(src));
}
__device__ __forceinline__ void cp_commit()
{
    asm volatile("cp.async.commit_group;");
}
__device__ __forceinline__ void cp_wait1()
{
    asm volatile("cp.async.wait_group 1;");
}
__device__ __forceinline__ uint32_t s2u(const void* p)
{
    uint32_t a;
    asm("{ .reg .u64 t; cvta.to.shared.u64 t, %1; cvt.u32.u64 %0, t; }"
        : "=r"(a) : "l"(p));
    return a;
}
__device__ __forceinline__ float ex2f(float x)
{
    float r;
    asm("ex2.approx.f32 %0, %1;" : "=f"(r) : "f"(x));
    return r;
}
__device__ __forceinline__ uint32_t packh2(float x0, float x1)
{
    __half2 h = __floats2half2_rn(x0, x1);
    return *(uint32_t*)&h;
}
// exact fp16 split of (x0,x1): h = fp16(x), l = fp16(x - h); h+l == x to 2^-24
__device__ __forceinline__ void splitpk_h(float x0, float x1,
                                          uint32_t& h, uint32_t& l)
{
    __half h0 = __float2half_rn(x0);
    __half h1 = __float2half_rn(x1);
    __half l0 = __float2half_rn(x0 - __half2float(h0));
    __half l1 = __float2half_rn(x1 - __half2float(h1));
    __half2 hh; hh.x = h0; hh.y = h1;
    __half2 ll; ll.x = l0; ll.y = l1;
    h = *(uint32_t*)&hh;
    l = *(uint32_t*)&ll;
}

// ---------------- prepass: convert K/V once into scratch ----------------
__global__ void __launch_bounds__(256, 4)
ta_prepass(const float* __restrict__ K, const float* __restrict__ V)
{
    extern __shared__ char ps[];
    const int tid  = threadIdx.x;
    const int tile = blockIdx.x;
    const int bh   = blockIdx.y;

    const float* Kt = K + ((size_t)bh * 1024 + (size_t)tile * 64) * 64;
    const float* Vt = V + ((size_t)bh * 1024 + (size_t)tile * 64) * 64;

    __half* Kh = (__half*)ps;                 // [kv][e], 64 x KST
    __half* Vh = (__half*)(ps + ARR_B);       // V^T: [e][kv], 64 x KST

    #pragma unroll
    for (int it = 0; it < 4; it++) {
        int i = tid + it * 256;
        int r = i >> 4, e4 = (i & 15) << 2;
        float4 kv = *(const float4*)(Kt + (size_t)r * 64 + e4);
        *(uint32_t*)&Kh[r * KST + e4]     = packh2(kv.x, kv.y);
        *(uint32_t*)&Kh[r * KST + e4 + 2] = packh2(kv.z, kv.w);
        float4 vv = *(const float4*)(Vt + (size_t)r * 64 + e4);
        Vh[(e4 + 0) * KST + r] = __float2half_rn(vv.x);
        Vh[(e4 + 1) * KST + r] = __float2half_rn(vv.y);
        Vh[(e4 + 2) * KST + r] = __float2half_rn(vv.z);
        Vh[(e4 + 3) * KST + r] = __float2half_rn(vv.w);
    }
    __syncthreads();

    unsigned char* dst = g_scratch + ((size_t)bh * 16 + tile) * TILE_B;
    for (uint32_t i = tid; i < CHUNKS; i += 256)
        *(float4*)(dst + i * 16) = *(const float4*)(ps + i * 16);
}

// ---------------- main kernel: 64 q-rows per CTA, 2 CTAs/SM ----------------
__global__ void __launch_bounds__(256, 2)
ta_attn_mma6(const float* __restrict__ Q, const float* __restrict__ TD,
             float* __restrict__ O)
{
    extern __shared__ char sm[];
    const uint32_t sbase = s2u(sm);

    const int tid  = threadIdx.x;
    const int warp = tid >> 5;
    const int lane = tid & 31;
    const int g    = lane >> 2;
    const int qd   = lane & 3;
    const int wm   = warp & 3;       // M slice: q rows wm*16 .. +15
    const int wn   = warp >> 2;      // N half:  kv cols wn*32 .. +31

    const int qt = blockIdx.x;       // q tile (0..15), 64 rows each
    const int bh = blockIdx.y;       // b*8+h (0..63)
    const int b  = bh >> 3;

    const float* Qb  = Q  + ((size_t)bh * 1024 + (size_t)qt * 64) * 64;
    const float* tdb = TD + (size_t)b * 1024 + (size_t)qt * 64;
    float*       Ob  = O  + ((size_t)bh * 1024 + (size_t)qt * 64) * 64;
    const unsigned char* src0 = g_scratch + (size_t)bh * 16 * TILE_B;

    const int ra = wm * 16 + g;      // accum rows ra, ra+8
    const int rb = ra + 8;

    // ldmatrix per-lane offset: rows (L&7)+((L>>4)<<3), +16B for bit3
    const uint32_t lmoff = (uint32_t)(((lane & 7) + ((lane >> 4) << 3)) * ROWB
                                      + ((lane >> 3) & 1) * 16);

    // ---- cp.async prologue: tiles 0 and 1 into stages 0,1 ----
    #pragma unroll
    for (int pt = 0; pt < 2; pt++) {
        uint32_t dst = sbase + pt * TILE_B;
        const unsigned char* src = src0 + (size_t)pt * TILE_B;
        for (uint32_t i = tid; i < CHUNKS; i += 256)
            cpasync16(dst + i * 16, src + i * 16);
        cp_commit();
    }

    // ---- Q A-fragments: exact fp16 pair, decay*SCALE*log2e folded ----
    uint32_t qh[4][4], ql[4][4];
    {
        const float ca = QSCALE_L2 * __expf(-tdb[ra] * FACTOR_INV);
        const float cb = QSCALE_L2 * __expf(-tdb[rb] * FACTOR_INV);
        #pragma unroll
        for (int k = 0; k < 4; k++) {
            int e = 16 * k + 2 * qd;
            float2 xa0 = *(const float2*)(Qb + (size_t)ra * 64 + e);
            float2 xb0 = *(const float2*)(Qb + (size_t)rb * 64 + e);
            float2 xa1 = *(const float2*)(Qb + (size_t)ra * 64 + e + 8);
            float2 xb1 = *(const float2*)(Qb + (size_t)rb * 64 + e + 8);
            splitpk_h(xa0.x * ca, xa0.y * ca, qh[k][0], ql[k][0]);
            splitpk_h(xb0.x * cb, xb0.y * cb, qh[k][1], ql[k][1]);
            splitpk_h(xa1.x * ca, xa1.y * ca, qh[k][2], ql[k][2]);
            splitpk_h(xb1.x * cb, xb1.y * cb, qh[k][3], ql[k][3]);
        }
    }

    float oacc[8][4];
    #pragma unroll
    for (int j = 0; j < 8; j++)
        #pragma unroll
        for (int c = 0; c < 4; c++) oacc[j][c] = 0.0f;
    float lsA = 0.0f, lsB = 0.0f;

    for (int t = 0; t < NTILES; t++) {
        cp_wait1();            // tile t landed (t+1 may be in flight)
        __syncthreads();

        // ---- issue tile t+2 into stage (t+2)%3 (its readers retired) ----
        if (t + 2 < NTILES) {
            uint32_t dst = sbase + ((t + 2) % 3) * TILE_B;
            const unsigned char* src = src0 + (size_t)(t + 2) * TILE_B;
            for (uint32_t i = tid; i < CHUNKS; i += 256)
                cpasync16(dst + i * 16, src + i * 16);
        }
        cp_commit();           // always commit to keep group accounting fixed

        const uint32_t buf = sbase + (t % 3) * TILE_B;
        const uint32_t kqb = buf + wn * (32 * ROWB) + lmoff;      // Kh half
        const uint32_t vvb = buf + ARR_B + wn * 64 + lmoff;       // Vh half

        // ---- S' = log2e*z - 18:  (qh + ql) x Kh, 2 fp16 terms ----
        float sacc[4][4];
        #pragma unroll
        for (int j = 0; j < 4; j++)
            #pragma unroll
            for (int c = 0; c < 4; c++) sacc[j][c] = EXP2_BIAS;

        #pragma unroll
        for (int k = 0; k < 4; k++) {
            #pragma unroll
            for (int jp = 0; jp < 2; jp++) {
                uint32_t b4[4];
                ldsm4(b4, kqb + jp * (16 * ROWB) + k * 32);
                mma_f16(sacc[2*jp],   qh[k][0], qh[k][1], qh[k][2], qh[k][3],
                        b4[0], b4[1]);
                mma_f16(sacc[2*jp],   ql[k][0], ql[k][1], ql[k][2], ql[k][3],
                        b4[0], b4[1]);
                mma_f16(sacc[2*jp+1], qh[k][0], qh[k][1], qh[k][2], qh[k][3],
                        b4[2], b4[3]);
                mma_f16(sacc[2*jp+1], ql[k][0], ql[k][1], ql[k][2], ql[k][3],
                        b4[2], b4[3]);
            }
        }

        // ---- p = 2^(sacc) directly; pack fp16 ----
        uint32_t ph[2][4];
        #pragma unroll
        for (int j = 0; j < 4; j++) {
            sacc[j][0] = ex2f(sacc[j][0]);
            sacc[j][1] = ex2f(sacc[j][1]);
            sacc[j][2] = ex2f(sacc[j][2]);
            sacc[j][3] = ex2f(sacc[j][3]);
            lsA += sacc[j][0] + sacc[j][1];
            lsB += sacc[j][2] + sacc[j][3];
        }
        #pragma unroll
        for (int kk = 0; kk < 2; kk++) {
            ph[kk][0] = packh2(sacc[2*kk][0],   sacc[2*kk][1]);
            ph[kk][1] = packh2(sacc[2*kk][2],   sacc[2*kk][3]);
            ph[kk][2] = packh2(sacc[2*kk+1][0], sacc[2*kk+1][1]);
            ph[kk][3] = packh2(sacc[2*kk+1][2], sacc[2*kk+1][3]);
        }

        // ---- O += P V over this warp's kv half (fp16), ldmatrix V frags ----
        #pragma unroll
        for (int kk = 0; kk < 2; kk++) {
            #pragma unroll
            for (int jp = 0; jp < 4; jp++) {
                uint32_t v4[4];
                ldsm4(v4, vvb + jp * (16 * ROWB) + kk * 32);
                mma_f16(oacc[2*jp],   ph[kk][0], ph[kk][1], ph[kk][2], ph[kk][3],
                        v4[0], v4[1]);
                mma_f16(oacc[2*jp+1], ph[kk][0], ph[kk][1], ph[kk][2], ph[kk][3],
                        v4[2], v4[3]);
            }
        }
    }

    // ---- quad-reduce row sums ----
    lsA += __shfl_xor_sync(0xffffffffu, lsA, 1);
    lsA += __shfl_xor_sync(0xffffffffu, lsA, 2);
    lsB += __shfl_xor_sync(0xffffffffu, lsB, 1);
    lsB += __shfl_xor_sync(0xffffffffu, lsB, 2);

    __syncthreads();   // all warps done with smem buffers before reuse

    // ---- epilogue: reduce O and lsum across the two N-halves via smem ----
    float* stage  = (float*)sm;              // 16 KB
    float* lstage = (float*)(sm + 16384);    // 256 B
    if (wn == 1) {
        #pragma unroll
        for (int j = 0; j < 8; j++) {
            float4 v4 = make_float4(oacc[j][0], oacc[j][1],
                                    oacc[j][2], oacc[j][3]);
            *(float4*)&stage[((wm * 8 + j) * 32 + lane) * 4] = v4;
        }
        lstage[ra] = lsA;
        lstage[rb] = lsB;
    }
    __syncthreads();
    if (wn == 0) {
        float invA = 1.0f / (lsA + lstage[ra]);
        float invB = 1.0f / (lsB + lstage[rb]);
        #pragma unroll
        for (int j = 0; j < 8; j++) {
            float4 p4 = *(float4*)&stage[((wm * 8 + j) * 32 + lane) * 4];
            float2 oa, ob;
            oa.x = (oacc[j][0] + p4.x) * invA;
            oa.y = (oacc[j][1] + p4.y) * invA;
            ob.x = (oacc[j][2] + p4.z) * invB;
            ob.y = (oacc[j][3] + p4.w) * invB;
            *(float2*)(Ob + (size_t)ra * 64 + 8 * j + 2 * qd) = oa;
            *(float2*)(Ob + (size_t)rb * 64 + 8 * j + 2 * qd) = ob;
        }
    }
}

extern "C" void kernel_launch(void* const* d_in, const int* in_sizes, int n_in,
                              void* d_out, int out_size)
{
    const float* Q  = (const float*)d_in[0];
    const float* K  = (const float*)d_in[1];
    const float* V  = (const float*)d_in[2];
    const float* TD = (const float*)d_in[3];
    float* O = (float*)d_out;

    cudaFuncSetAttribute(ta_prepass,
                         cudaFuncAttributeMaxDynamicSharedMemorySize, TILE_B);
    cudaFuncSetAttribute(ta_attn_mma6,
                         cudaFuncAttributeMaxDynamicSharedMemorySize, SMEM_B);

    dim3 pgrid(16, 64);   // 16 kv tiles x 64 (b,h)
    ta_prepass<<<pgrid, 256, TILE_B>>>(K, V);

    dim3 grid(16, 64);    // 16 q-tiles (64 rows) x 64 (b,h); 2 CTAs/SM
    ta_attn_mma6<<<grid, 256, SMEM_B>>>(Q, TD, O);
}